// round 5
// baseline (speedup 1.0000x reference)
#include <cuda_runtime.h>
#include <cstdint>

#define SEQ 4096
#define HDIM 64
#define NTILES (SEQ / 32)

struct __align__(16) KFragTile { uint2 hi[4][32][4]; uint2 lo[4][32][4]; };  // 8 KB
struct __align__(16) VFragTile { uint2 hi[2][64][4]; uint2 lo[2][64][4]; };  // 8 KB

__device__ KFragTile g_kf[16][NTILES];   // 16 MB scratch
__device__ VFragTile g_vf[16][NTILES];   // 16 MB scratch

__device__ __forceinline__ uint32_t pack2(float e_lo, float e_hi) {
    uint32_t r;
    asm("cvt.rn.bf16x2.f32 %0, %1, %2;" : "=r"(r) : "f"(e_hi), "f"(e_lo));
    return r;
}
__device__ __forceinline__ void split2(float e0, float e1, uint32_t& h, uint32_t& l) {
    h = pack2(e0, e1);
    float h0 = __uint_as_float(h << 16);
    float h1 = __uint_as_float(h & 0xffff0000u);
    l = pack2(e0 - h0, e1 - h1);
}
__device__ __forceinline__ void mma_bf16(float* c, const uint32_t* a, uint32_t b0, uint32_t b1) {
    asm volatile("mma.sync.aligned.m16n8k16.row.col.f32.bf16.bf16.f32 "
                 "{%0,%1,%2,%3}, {%4,%5,%6,%7}, {%8,%9}, {%0,%1,%2,%3};"
                 : "+f"(c[0]), "+f"(c[1]), "+f"(c[2]), "+f"(c[3])
                 : "r"(a[0]), "r"(a[1]), "r"(a[2]), "r"(a[3]), "r"(b0), "r"(b1));
}
__device__ __forceinline__ void cpa16(uint32_t s, const void* g) {
    asm volatile("cp.async.cg.shared.global [%0], [%1], 16;" :: "r"(s), "l"(g));
}

// ---------------- pre-pass: split K/V once into MMA-fragment layout ----------------
__global__ __launch_bounds__(128)
void presplit_kv(const float* __restrict__ k, const float* __restrict__ v)
{
    __shared__ __align__(16) struct { float kraw[64][32]; float vraw[32][64]; } sm;
    const int t = blockIdx.x, h = blockIdx.y, tid = threadIdx.x;
    const int lane = tid & 31, w = tid >> 5;
    const int j0 = 32 * t;
    const float* kh = k + (size_t)h * HDIM * SEQ;   // [D][S]
    const float* vh = v + (size_t)h * SEQ * HDIM;

    for (int i4 = tid; i4 < 512; i4 += 128) {
        int d = i4 >> 3, j4 = (i4 & 7) * 4;
        *(float4*)&sm.kraw[d][j4] = *(const float4*)&kh[(size_t)d * SEQ + j0 + j4];
    }
    for (int i4 = tid; i4 < 512; i4 += 128) {
        int jj = i4 >> 4, d4 = (i4 & 15) * 4;
        *(float4*)&sm.vraw[jj][d4] = *(const float4*)&vh[(size_t)(j0 + jj) * HDIM + d4];
    }
    __syncthreads();

    {   // K: thread owns (chunk kt=w, key=lane)
        float f[16];
        #pragma unroll
        for (int kk = 0; kk < 16; kk++) f[kk] = sm.kraw[16 * w + kk][lane];
        uint32_t wh[8], wl[8];
        #pragma unroll
        for (int x = 0; x < 8; x++) split2(f[2 * x], f[2 * x + 1], wh[x], wl[x]);
        uint4* dh = (uint4*)&g_kf[h][t].hi[w][lane][0];
        dh[0] = make_uint4(wh[0], wh[4], wh[1], wh[5]);
        dh[1] = make_uint4(wh[2], wh[6], wh[3], wh[7]);
        uint4* dl = (uint4*)&g_kf[h][t].lo[w][lane][0];
        dl[0] = make_uint4(wl[0], wl[4], wl[1], wl[5]);
        dl[1] = make_uint4(wl[2], wl[6], wl[3], wl[7]);
    }
    {   // V: thread owns (chunk vjt, d-col vn)
        const int vjt = tid >> 6, vn = tid & 63;
        float f[16];
        #pragma unroll
        for (int kk = 0; kk < 16; kk++) f[kk] = sm.vraw[16 * vjt + kk][vn];
        uint32_t wh[8], wl[8];
        #pragma unroll
        for (int x = 0; x < 8; x++) split2(f[2 * x], f[2 * x + 1], wh[x], wl[x]);
        uint4* dh = (uint4*)&g_vf[h][t].hi[vjt][vn][0];
        dh[0] = make_uint4(wh[0], wh[4], wh[1], wh[5]);
        dh[1] = make_uint4(wh[2], wh[6], wh[3], wh[7]);
        uint4* dl = (uint4*)&g_vf[h][t].lo[vjt][vn][0];
        dl[0] = make_uint4(wl[0], wl[4], wl[1], wl[5]);
        dl[1] = make_uint4(wl[2], wl[6], wl[3], wl[7]);
    }
}

// ---------------- main: flash attention, double-buffered fragment tiles ----------------
struct __align__(16) SmemMain {
    union {
        struct { KFragTile k[2]; VFragTile v[2]; } b;   // 32 KB
        float qstage[64][68];
    };
};

__global__ __launch_bounds__(128, 3)
void attn_bf16x3_flash(const float* __restrict__ q, float* __restrict__ out)
{
    __shared__ SmemMain sm;
    const int tid  = threadIdx.x;
    const int lane = tid & 31;
    const int w    = tid >> 5;
    const int qb   = (int)gridDim.x - 1 - (int)blockIdx.x;   // heavy blocks first
    const int h    = blockIdx.y;
    const int r    = lane >> 2;
    const int c    = lane & 3;

    const float* qh = q + (size_t)h * SEQ * HDIM;

    // ---- Q block -> bf16 hi/lo A-fragments (scale 1/8 folded) ----
    {
        const float4* qg = (const float4*)(qh + (size_t)qb * 64 * HDIM);
        for (int i4 = tid; i4 < 64 * 16; i4 += 128) {
            int row = i4 >> 4, d4 = i4 & 15;
            *(float4*)&sm.qstage[row][4 * d4] = qg[i4];
        }
    }
    __syncthreads();
    uint32_t qhi[4][4], qlo[4][4];
    {
        const int r0 = w * 16 + r, r1 = r0 + 8;
        #pragma unroll
        for (int kt = 0; kt < 4; kt++) {
            float2 x0 = *(float2*)&sm.qstage[r0][16 * kt + 2 * c];
            float2 x1 = *(float2*)&sm.qstage[r1][16 * kt + 2 * c];
            float2 x2 = *(float2*)&sm.qstage[r0][16 * kt + 2 * c + 8];
            float2 x3 = *(float2*)&sm.qstage[r1][16 * kt + 2 * c + 8];
            split2(x0.x * 0.125f, x0.y * 0.125f, qhi[kt][0], qlo[kt][0]);
            split2(x1.x * 0.125f, x1.y * 0.125f, qhi[kt][1], qlo[kt][1]);
            split2(x2.x * 0.125f, x2.y * 0.125f, qhi[kt][2], qlo[kt][2]);
            split2(x3.x * 0.125f, x3.y * 0.125f, qhi[kt][3], qlo[kt][3]);
        }
    }
    __syncthreads();   // qstage dead; buffers live

    float oacc[8][4];
    #pragma unroll
    for (int nt = 0; nt < 8; nt++)
        #pragma unroll
        for (int i = 0; i < 4; i++) oacc[nt][i] = 0.f;
    float m0 = -1e30f, m1 = -1e30f, l0 = 0.f, l1 = 0.f;

    const int row0 = qb * 64 + w * 16 + r;
    const int row1 = row0 + 8;

    auto stage = [&](int t, int buf) {
        const char* srck = (const char*)&g_kf[h][t];
        const char* srcv = (const char*)&g_vf[h][t];
        uint32_t dk = (uint32_t)__cvta_generic_to_shared(&sm.b.k[buf]);
        uint32_t dv = (uint32_t)__cvta_generic_to_shared(&sm.b.v[buf]);
        #pragma unroll
        for (int it = 0; it < 4; it++) {
            uint32_t off = (uint32_t)(tid + 128 * it) * 16u;
            cpa16(dk + off, srck + off);
        }
        #pragma unroll
        for (int it = 0; it < 4; it++) {
            uint32_t off = (uint32_t)(tid + 128 * it) * 16u;
            cpa16(dv + off, srcv + off);
        }
        asm volatile("cp.async.commit_group;");
    };

    auto compute = [&](int t, int buf) {
        const int j0 = 32 * t;
        if (j0 > qb * 64 + w * 16 + 15) return;   // warp fully masked

        const KFragTile& KT = sm.b.k[buf];
        const VFragTile& VT = sm.b.v[buf];

        float sacc[4][4];
        #pragma unroll
        for (int nt = 0; nt < 4; nt++)
            #pragma unroll
            for (int i = 0; i < 4; i++) sacc[nt][i] = 0.f;
        #pragma unroll
        for (int kt = 0; kt < 4; kt++) {
            #pragma unroll
            for (int nt = 0; nt < 4; nt++) {
                uint2 bh = KT.hi[kt][8 * nt + r][c];
                uint2 bl = KT.lo[kt][8 * nt + r][c];
                mma_bf16(sacc[nt], qlo[kt], bh.x, bh.y);
                mma_bf16(sacc[nt], qhi[kt], bl.x, bl.y);
                mma_bf16(sacc[nt], qhi[kt], bh.x, bh.y);
            }
        }

        if (j0 + 31 > qb * 64 + w * 16) {   // diagonal tiles: elementwise mask
            #pragma unroll
            for (int nt = 0; nt < 4; nt++) {
                int col = j0 + 8 * nt + 2 * c;
                if (col     > row0) sacc[nt][0] = -1e30f;
                if (col + 1 > row0) sacc[nt][1] = -1e30f;
                if (col     > row1) sacc[nt][2] = -1e30f;
                if (col + 1 > row1) sacc[nt][3] = -1e30f;
            }
        }

        float mx0 = sacc[0][0], mx1 = sacc[0][2];
        #pragma unroll
        for (int nt = 0; nt < 4; nt++) {
            mx0 = fmaxf(mx0, fmaxf(sacc[nt][0], sacc[nt][1]));
            mx1 = fmaxf(mx1, fmaxf(sacc[nt][2], sacc[nt][3]));
        }
        mx0 = fmaxf(mx0, __shfl_xor_sync(0xffffffffu, mx0, 1));
        mx0 = fmaxf(mx0, __shfl_xor_sync(0xffffffffu, mx0, 2));
        mx1 = fmaxf(mx1, __shfl_xor_sync(0xffffffffu, mx1, 1));
        mx1 = fmaxf(mx1, __shfl_xor_sync(0xffffffffu, mx1, 2));

        const float nm0 = fmaxf(m0, mx0), nm1 = fmaxf(m1, mx1);
        const float cor0 = __expf(m0 - nm0), cor1 = __expf(m1 - nm1);
        l0 *= cor0; l1 *= cor1;
        #pragma unroll
        for (int nt = 0; nt < 8; nt++) {
            oacc[nt][0] *= cor0; oacc[nt][1] *= cor0;
            oacc[nt][2] *= cor1; oacc[nt][3] *= cor1;
        }

        uint32_t ph[4][2], pl[4][2];
        float sum0 = 0.f, sum1 = 0.f;
        #pragma unroll
        for (int nt = 0; nt < 4; nt++) {
            float p00 = __expf(sacc[nt][0] - nm0);
            float p01 = __expf(sacc[nt][1] - nm0);
            float p10 = __expf(sacc[nt][2] - nm1);
            float p11 = __expf(sacc[nt][3] - nm1);
            sum0 += p00 + p01; sum1 += p10 + p11;
            split2(p00, p01, ph[nt][0], pl[nt][0]);
            split2(p10, p11, ph[nt][1], pl[nt][1]);
        }
        sum0 += __shfl_xor_sync(0xffffffffu, sum0, 1);
        sum0 += __shfl_xor_sync(0xffffffffu, sum0, 2);
        sum1 += __shfl_xor_sync(0xffffffffu, sum1, 1);
        sum1 += __shfl_xor_sync(0xffffffffu, sum1, 2);
        l0 += sum0; l1 += sum1;
        m0 = nm0; m1 = nm1;

        #pragma unroll
        for (int jt = 0; jt < 2; jt++) {
            uint32_t ah[4] = {ph[2*jt][0], ph[2*jt][1], ph[2*jt+1][0], ph[2*jt+1][1]};
            uint32_t al[4] = {pl[2*jt][0], pl[2*jt][1], pl[2*jt+1][0], pl[2*jt+1][1]};
            #pragma unroll
            for (int nt = 0; nt < 8; nt++) {
                uint2 bh = VT.hi[jt][8 * nt + r][c];
                uint2 bl = VT.lo[jt][8 * nt + r][c];
                mma_bf16(oacc[nt], al, bh.x, bh.y);
                mma_bf16(oacc[nt], ah, bl.x, bl.y);
                mma_bf16(oacc[nt], ah, bh.x, bh.y);
            }
        }
    };

    const int ntile = 2 * (qb + 1);
    stage(0, 0);
    for (int t = 0; t < ntile; t++) {
        const int cur = t & 1;
        if (t + 1 < ntile) {
            stage(t + 1, cur ^ 1);
            asm volatile("cp.async.wait_group 1;" ::: "memory");
        } else {
            asm volatile("cp.async.wait_group 0;" ::: "memory");
        }
        __syncthreads();          // tile t data visible to all
        compute(t, cur);
        __syncthreads();          // tile t reads done before buf reuse
    }

    const float inv0 = 1.f / l0, inv1 = 1.f / l1;
    float* o0 = out + ((size_t)h * SEQ + row0) * HDIM;
    float* o1 = out + ((size_t)h * SEQ + row1) * HDIM;
    #pragma unroll
    for (int nt = 0; nt < 8; nt++) {
        int col = 8 * nt + 2 * c;
        *(float2*)&o0[col] = make_float2(oacc[nt][0] * inv0, oacc[nt][1] * inv0);
        *(float2*)&o1[col] = make_float2(oacc[nt][2] * inv1, oacc[nt][3] * inv1);
    }
}

extern "C" void kernel_launch(void* const* d_in, const int* in_sizes, int n_in,
                              void* d_out, int out_size)
{
    const float* q = (const float*)d_in[0];
    const float* k = (const float*)d_in[1];
    const float* v = (const float*)d_in[2];
    float* out = (float*)d_out;

    dim3 pgrid(NTILES, 16, 1);
    presplit_kv<<<pgrid, 128>>>(k, v);          // once per launch, ~15 us

    dim3 grid(SEQ / 64, 16, 1);
    attn_bf16x3_flash<<<grid, 128>>>(q, out);
}

// round 6
// speedup vs baseline: 1.0185x; 1.0185x over previous
#include <cuda_runtime.h>
#include <cstdint>

#define SEQ 4096
#define HDIM 64

struct __align__(16) Smem {
    uint4 kf[4][32][4];   // [k16-chunk][key][c] = (hi_c, hi_{c+4}, lo_c, lo_{c+4})
    uint4 vf[2][64][4];   // [key16-chunk][d][c]
    union {
        struct { float kraw[64][32]; float vraw[32][64]; } r;
        float qstage[64][72];
    } u;
};

__device__ __forceinline__ uint32_t pack2(float e_lo, float e_hi) {
    uint32_t r;
    asm("cvt.rn.bf16x2.f32 %0, %1, %2;" : "=r"(r) : "f"(e_hi), "f"(e_lo));
    return r;
}
__device__ __forceinline__ void split2(float e0, float e1, uint32_t& h, uint32_t& l) {
    h = pack2(e0, e1);
    float h0 = __uint_as_float(h << 16);
    float h1 = __uint_as_float(h & 0xffff0000u);
    l = pack2(e0 - h0, e1 - h1);
}
__device__ __forceinline__ void mma_bf16(float* c, const uint32_t* a, uint32_t b0, uint32_t b1) {
    asm volatile("mma.sync.aligned.m16n8k16.row.col.f32.bf16.bf16.f32 "
                 "{%0,%1,%2,%3}, {%4,%5,%6,%7}, {%8,%9}, {%0,%1,%2,%3};"
                 : "+f"(c[0]), "+f"(c[1]), "+f"(c[2]), "+f"(c[3])
                 : "r"(a[0]), "r"(a[1]), "r"(a[2]), "r"(a[3]), "r"(b0), "r"(b1));
}
__device__ __forceinline__ void cpa16(uint32_t s, const void* g) {
    asm volatile("cp.async.cg.shared.global [%0], [%1], 16;" :: "r"(s), "l"(g));
}
__device__ __forceinline__ float ex2(float x) {
    float y; asm("ex2.approx.ftz.f32 %0, %1;" : "=f"(y) : "f"(x)); return y;
}

__global__ __launch_bounds__(128, 4)
void attn_bf16x3_flash(const float* __restrict__ q, const float* __restrict__ k,
                       const float* __restrict__ v, float* __restrict__ out)
{
    __shared__ Smem sm;
    const int tid  = threadIdx.x;
    const int lane = tid & 31;
    const int w    = tid >> 5;
    const int qb   = (int)gridDim.x - 1 - (int)blockIdx.x;   // heavy blocks first
    const int h    = blockIdx.y;
    const int r    = lane >> 2;
    const int c    = lane & 3;

    const float* qh = q + (size_t)h * SEQ * HDIM;
    const float* kh = k + (size_t)h * HDIM * SEQ;            // [D][S]
    const float* vh = v + (size_t)h * SEQ * HDIM;

    // ---- Q block -> bf16 hi/lo A-fragments; fold 1/8 * log2(e) into scale ----
    const float QSC = 0.125f * 1.4426950408889634f;
    {
        const float4* qg = (const float4*)(qh + (size_t)qb * 64 * HDIM);
        for (int i4 = tid; i4 < 64 * 16; i4 += 128) {
            int row = i4 >> 4, d4 = i4 & 15;
            *(float4*)&sm.u.qstage[row][4 * d4] = qg[i4];
        }
    }
    __syncthreads();
    uint32_t qhi[4][4], qlo[4][4];
    {
        const int r0 = w * 16 + r, r1 = r0 + 8;
        #pragma unroll
        for (int kt = 0; kt < 4; kt++) {
            float2 x0 = *(float2*)&sm.u.qstage[r0][16 * kt + 2 * c];
            float2 x1 = *(float2*)&sm.u.qstage[r1][16 * kt + 2 * c];
            float2 x2 = *(float2*)&sm.u.qstage[r0][16 * kt + 2 * c + 8];
            float2 x3 = *(float2*)&sm.u.qstage[r1][16 * kt + 2 * c + 8];
            split2(x0.x * QSC, x0.y * QSC, qhi[kt][0], qlo[kt][0]);
            split2(x1.x * QSC, x1.y * QSC, qhi[kt][1], qlo[kt][1]);
            split2(x2.x * QSC, x2.y * QSC, qhi[kt][2], qlo[kt][2]);
            split2(x3.x * QSC, x3.y * QSC, qhi[kt][3], qlo[kt][3]);
        }
    }
    __syncthreads();

    const uint32_t kraw_s = (uint32_t)__cvta_generic_to_shared(&sm.u.r.kraw[0][0]);
    const uint32_t vraw_s = (uint32_t)__cvta_generic_to_shared(&sm.u.r.vraw[0][0]);

    float oacc[8][4];
    #pragma unroll
    for (int nt = 0; nt < 8; nt++)
        #pragma unroll
        for (int i = 0; i < 4; i++) oacc[nt][i] = 0.f;
    float m0 = -1e30f, m1 = -1e30f, l0 = 0.f, l1 = 0.f;

    const int row0 = qb * 64 + w * 16 + r;
    const int row1 = row0 + 8;
    const int vjt  = tid >> 6;
    const int vn   = tid & 63;

    auto stage = [&](int t) {
        const int j0 = 32 * t;
        #pragma unroll
        for (int it = 0; it < 4; it++) {
            int i4 = tid + 128 * it;
            int d = i4 >> 3, j4 = (i4 & 7) * 4;
            cpa16(kraw_s + (uint32_t)(d * 32 + j4) * 4u, kh + (size_t)d * SEQ + j0 + j4);
        }
        #pragma unroll
        for (int it = 0; it < 4; it++) {
            int i4 = tid + 128 * it;
            int jj = i4 >> 4, d4 = (i4 & 15) * 4;
            cpa16(vraw_s + (uint32_t)(jj * 64 + d4) * 4u, vh + (size_t)(j0 + jj) * HDIM + d4);
        }
        asm volatile("cp.async.commit_group;");
    };

    auto convert = [&]() {
        {   // K: thread owns (chunk kt=w, key=lane)
            float f[16];
            #pragma unroll
            for (int kk = 0; kk < 16; kk++) f[kk] = sm.u.r.kraw[16 * w + kk][lane];
            uint32_t wh[8], wl[8];
            #pragma unroll
            for (int x = 0; x < 8; x++) split2(f[2 * x], f[2 * x + 1], wh[x], wl[x]);
            sm.kf[w][lane][0] = make_uint4(wh[0], wh[4], wl[0], wl[4]);
            sm.kf[w][lane][1] = make_uint4(wh[1], wh[5], wl[1], wl[5]);
            sm.kf[w][lane][2] = make_uint4(wh[2], wh[6], wl[2], wl[6]);
            sm.kf[w][lane][3] = make_uint4(wh[3], wh[7], wl[3], wl[7]);
        }
        {   // V: thread owns (chunk vjt, d-col vn)
            float f[16];
            #pragma unroll
            for (int kk = 0; kk < 16; kk++) f[kk] = sm.u.r.vraw[16 * vjt + kk][vn];
            uint32_t wh[8], wl[8];
            #pragma unroll
            for (int x = 0; x < 8; x++) split2(f[2 * x], f[2 * x + 1], wh[x], wl[x]);
            sm.vf[vjt][vn][0] = make_uint4(wh[0], wh[4], wl[0], wl[4]);
            sm.vf[vjt][vn][1] = make_uint4(wh[1], wh[5], wl[1], wl[5]);
            sm.vf[vjt][vn][2] = make_uint4(wh[2], wh[6], wl[2], wl[6]);
            sm.vf[vjt][vn][3] = make_uint4(wh[3], wh[7], wl[3], wl[7]);
        }
    };

    auto compute = [&](int t) {
        const int j0 = 32 * t;
        if (j0 > qb * 64 + w * 16 + 15) return;   // warp fully masked

        float sacc[4][4];
        #pragma unroll
        for (int nt = 0; nt < 4; nt++)
            #pragma unroll
            for (int i = 0; i < 4; i++) sacc[nt][i] = 0.f;
        #pragma unroll
        for (int kt = 0; kt < 4; kt++) {
            #pragma unroll
            for (int nt = 0; nt < 4; nt++) {
                uint4 f = sm.kf[kt][8 * nt + r][c];
                mma_bf16(sacc[nt], qlo[kt], f.x, f.y);
                mma_bf16(sacc[nt], qhi[kt], f.z, f.w);
                mma_bf16(sacc[nt], qhi[kt], f.x, f.y);
            }
        }

        if (j0 + 31 > qb * 64 + w * 16) {   // diagonal tiles: elementwise mask
            #pragma unroll
            for (int nt = 0; nt < 4; nt++) {
                int col = j0 + 8 * nt + 2 * c;
                if (col     > row0) sacc[nt][0] = -1e30f;
                if (col + 1 > row0) sacc[nt][1] = -1e30f;
                if (col     > row1) sacc[nt][2] = -1e30f;
                if (col + 1 > row1) sacc[nt][3] = -1e30f;
            }
        }

        float mx0 = sacc[0][0], mx1 = sacc[0][2];
        #pragma unroll
        for (int nt = 0; nt < 4; nt++) {
            mx0 = fmaxf(mx0, fmaxf(sacc[nt][0], sacc[nt][1]));
            mx1 = fmaxf(mx1, fmaxf(sacc[nt][2], sacc[nt][3]));
        }
        mx0 = fmaxf(mx0, __shfl_xor_sync(0xffffffffu, mx0, 1));
        mx0 = fmaxf(mx0, __shfl_xor_sync(0xffffffffu, mx0, 2));
        mx1 = fmaxf(mx1, __shfl_xor_sync(0xffffffffu, mx1, 1));
        mx1 = fmaxf(mx1, __shfl_xor_sync(0xffffffffu, mx1, 2));

        const float nm0 = fmaxf(m0, mx0), nm1 = fmaxf(m1, mx1);
        const float cor0 = ex2(m0 - nm0), cor1 = ex2(m1 - nm1);  // log2 domain
        l0 *= cor0; l1 *= cor1;
        #pragma unroll
        for (int nt = 0; nt < 8; nt++) {
            oacc[nt][0] *= cor0; oacc[nt][1] *= cor0;
            oacc[nt][2] *= cor1; oacc[nt][3] *= cor1;
        }

        uint32_t ph[4][2], pl[4][2];
        float sum0 = 0.f, sum1 = 0.f;
        #pragma unroll
        for (int nt = 0; nt < 4; nt++) {
            float p00 = ex2(sacc[nt][0] - nm0);
            float p01 = ex2(sacc[nt][1] - nm0);
            float p10 = ex2(sacc[nt][2] - nm1);
            float p11 = ex2(sacc[nt][3] - nm1);
            sum0 += p00 + p01; sum1 += p10 + p11;
            split2(p00, p01, ph[nt][0], pl[nt][0]);
            split2(p10, p11, ph[nt][1], pl[nt][1]);
        }
        sum0 += __shfl_xor_sync(0xffffffffu, sum0, 1);
        sum0 += __shfl_xor_sync(0xffffffffu, sum0, 2);
        sum1 += __shfl_xor_sync(0xffffffffu, sum1, 1);
        sum1 += __shfl_xor_sync(0xffffffffu, sum1, 2);
        l0 += sum0; l1 += sum1;
        m0 = nm0; m1 = nm1;

        #pragma unroll
        for (int jt = 0; jt < 2; jt++) {
            uint32_t ah[4] = {ph[2*jt][0], ph[2*jt][1], ph[2*jt+1][0], ph[2*jt+1][1]};
            uint32_t al[4] = {pl[2*jt][0], pl[2*jt][1], pl[2*jt+1][0], pl[2*jt+1][1]};
            #pragma unroll
            for (int nt = 0; nt < 8; nt++) {
                uint4 f = sm.vf[jt][8 * nt + r][c];
                mma_bf16(oacc[nt], al, f.x, f.y);
                mma_bf16(oacc[nt], ah, f.z, f.w);
                mma_bf16(oacc[nt], ah, f.x, f.y);
            }
        }
    };

    const int ntile = 2 * (qb + 1);
    stage(0);
    asm volatile("cp.async.wait_group 0;" ::: "memory");
    __syncthreads();
    convert();
    __syncthreads();
    for (int t = 0; t < ntile; t++) {
        if (t + 1 < ntile) stage(t + 1);      // overlaps compute(t)
        compute(t);
        if (t + 1 < ntile) {
            asm volatile("cp.async.wait_group 0;" ::: "memory");
            __syncthreads();
            convert();
            __syncthreads();
        }
    }

    const float inv0 = 1.f / l0, inv1 = 1.f / l1;
    float* o0 = out + ((size_t)h * SEQ + row0) * HDIM;
    float* o1 = out + ((size_t)h * SEQ + row1) * HDIM;
    #pragma unroll
    for (int nt = 0; nt < 8; nt++) {
        int col = 8 * nt + 2 * c;
        *(float2*)&o0[col] = make_float2(oacc[nt][0] * inv0, oacc[nt][1] * inv0);
        *(float2*)&o1[col] = make_float2(oacc[nt][2] * inv1, oacc[nt][3] * inv1);
    }
}

extern "C" void kernel_launch(void* const* d_in, const int* in_sizes, int n_in,
                              void* d_out, int out_size)
{
    const float* q = (const float*)d_in[0];
    const float* k = (const float*)d_in[1];
    const float* v = (const float*)d_in[2];
    float* out = (float*)d_out;

    dim3 grid(SEQ / 64, 16, 1);
    attn_bf16x3_flash<<<grid, 128>>>(q, k, v, out);
}